// round 1
// baseline (speedup 1.0000x reference)
#include <cuda_runtime.h>
#include <cstdint>

#define G_TOT   1024
#define WSZ     16
#define HDIM    16
#define B_ROWS  8192
#define GTILE   32                    // groups per block
#define HSPLIT  8                     // threads per group along H (2 h each)
#define BLOCK   (GTILE * HSPLIT)      // 256 threads
#define CHUNK_ROWS 8
#define STAGES  3
#define BTILES  14                    // 32*14 = 448 blocks ~= 148 SM * 3 CTA

__device__ __forceinline__ unsigned long long pack2(float lo, float hi) {
    unsigned long long r;
    asm("mov.b64 %0, {%1, %2};" : "=l"(r) : "f"(lo), "f"(hi));
    return r;
}
__device__ __forceinline__ void unpack2(unsigned long long v, float& lo, float& hi) {
    asm("mov.b64 {%0, %1}, %2;" : "=f"(lo), "=f"(hi) : "l"(v));
}
// d = a * b + d  (packed f32x2 — sm_100+ only, ptxas never auto-emits this)
__device__ __forceinline__ void ffma2(unsigned long long& d,
                                      unsigned long long a, unsigned long long b) {
    asm("fma.rn.f32x2 %0, %1, %2, %0;" : "+l"(d) : "l"(a), "l"(b));
}
__device__ __forceinline__ uint32_t smem_u32(const void* p) {
    return (uint32_t)__cvta_generic_to_shared(p);
}
__device__ __forceinline__ void cp_async16(uint32_t dst, const void* src) {
    asm volatile("cp.async.cg.shared.global [%0], [%1], 16;" :: "r"(dst), "l"(src));
}

__global__ void __launch_bounds__(BLOCK, 3)
bd_kernel(const float* __restrict__ x, const float* __restrict__ W,
          float* __restrict__ out)
{
    // 3 stages * 8 rows * 32 groups * 16 floats * 4B = 48 KB (static limit OK)
    __shared__ float xs[STAGES][CHUNK_ROWS * GTILE * WSZ];

    const int tid = threadIdx.x;
    const int hq  = tid & (HSPLIT - 1);   // which h-pair (0..7)
    const int gl  = tid >> 3;             // local group (0..31)
    const int gt  = blockIdx.x % (G_TOT / GTILE);
    const int bt  = blockIdx.x / (G_TOT / GTILE);
    const int g   = gt * GTILE + gl;

    const int r0 = (int)((long long)bt       * B_ROWS / BTILES);
    const int r1 = (int)((long long)(bt + 1) * B_ROWS / BTILES);

    // ---- weights -> registers, pre-paired over k: w2[k2][h] = (W[2k2][h], W[2k2+1][h])
    unsigned long long w2[WSZ / 2][2];
    {
        const float* wg = W + (size_t)g * (WSZ * HDIM) + hq * 2;
#pragma unroll
        for (int k2 = 0; k2 < WSZ / 2; ++k2) {
            float2 a = *(const float2*)(wg + (2 * k2)     * HDIM);
            float2 b = *(const float2*)(wg + (2 * k2 + 1) * HDIM);
            w2[k2][0] = pack2(a.x, b.x);
            w2[k2][1] = pack2(a.y, b.y);
        }
    }

    const int nChunks = (r1 - r0 + CHUNK_ROWS - 1) / CHUNK_ROWS;
    const float* xsrc = x + (size_t)gt * (GTILE * WSZ);   // column offset of this g-tile

    // chunk loader: 16 KB = 1024 x 16B, 4 cp.async per thread, fully coalesced
    auto load_chunk = [&](int c, int slot) {
#pragma unroll
        for (int j = 0; j < 4; ++j) {
            int idx = tid + j * BLOCK;        // 0..1023
            int rl  = idx >> 7;               // row within chunk (128 x 16B per row)
            int off = idx & 127;              // 16B unit within 2KB row slice
            int row = r0 + c * CHUNK_ROWS + rl;
            if (row < r1) {
                uint32_t dst = smem_u32(&xs[slot][rl * (GTILE * WSZ)]) + off * 16;
                const void* src =
                    (const char*)(xsrc + (size_t)row * (G_TOT * WSZ)) + off * 16;
                cp_async16(dst, src);
            }
        }
        asm volatile("cp.async.commit_group;");
    };

    // ---- prologue: fill pipeline
    for (int c = 0; c < STAGES - 1 && c < nChunks; ++c) load_chunk(c, c % STAGES);
    for (int c = nChunks; c < STAGES - 1; ++c)
        asm volatile("cp.async.commit_group;");

    // ---- main loop
    for (int c = 0; c < nChunks; ++c) {
        asm volatile("cp.async.wait_group %0;" :: "n"(STAGES - 2));
        __syncthreads();

        const int slot     = c % STAGES;
        const int base_row = r0 + c * CHUNK_ROWS;
        const int rows     = min(CHUNK_ROWS, r1 - base_row);
        const float* xrow0 = &xs[slot][gl * WSZ];
        float* optr = out + (size_t)base_row * (G_TOT * HDIM)
                          + (size_t)g * HDIM + hq * 2;

#pragma unroll
        for (int rl = 0; rl < CHUNK_ROWS; ++rl) {
            if (rl >= rows) break;  // uniform across block
            const ulonglong2* xq =
                (const ulonglong2*)(xrow0 + rl * (GTILE * WSZ));
            ulonglong2 q0 = xq[0], q1 = xq[1], q2 = xq[2], q3 = xq[3];
            unsigned long long xv[8] = {q0.x, q0.y, q1.x, q1.y,
                                        q2.x, q2.y, q3.x, q3.y};
            unsigned long long a0 = 0ull, a1 = 0ull;  // bits of (0.f, 0.f)
#pragma unroll
            for (int k2 = 0; k2 < 8; ++k2) {
                ffma2(a0, xv[k2], w2[k2][0]);
                ffma2(a1, xv[k2], w2[k2][1]);
            }
            float l0, h0, l1, h1;
            unpack2(a0, l0, h0);
            unpack2(a1, l1, h1);
            float2 o;
            o.x = fmaxf(l0 + h0, 0.0f);   // k-pair horizontal reduce + ReLU
            o.y = fmaxf(l1 + h1, 0.0f);
            *(float2*)optr = o;           // warp writes 256B contiguous
            optr += G_TOT * HDIM;
        }

        __syncthreads();  // all reads of slot (c+STAGES-1)%STAGES's old data done
        if (c + STAGES - 1 < nChunks)
            load_chunk(c + STAGES - 1, (c + STAGES - 1) % STAGES);
        else
            asm volatile("cp.async.commit_group;");
    }
}

extern "C" void kernel_launch(void* const* d_in, const int* in_sizes, int n_in,
                              void* d_out, int out_size) {
    const float* x = (const float*)d_in[0];   // (8192, 16384) f32
    const float* W = (const float*)d_in[1];   // (1024, 16, 16) f32
    float* out = (float*)d_out;               // (8192, 16384) f32
    dim3 grid((G_TOT / GTILE) * BTILES);      // 448 blocks
    bd_kernel<<<grid, BLOCK>>>(x, W, out);
}

// round 2
// speedup vs baseline: 1.0362x; 1.0362x over previous
#include <cuda_runtime.h>
#include <cstdint>

#define G_TOT   1024
#define WSZ     16
#define HDIM    16
#define B_ROWS  8192
#define GTILE   32                    // groups per block
#define HSPLIT  8                     // threads per group along H (2 h each)
#define BLOCK   (GTILE * HSPLIT)      // 256 threads
#define CHUNK_ROWS 8
#define STAGES  3
#define ROWSTRIDE (G_TOT * WSZ)       // 16384 floats per x/out row
#define CHUNKS_PER_GT (B_ROWS / CHUNK_ROWS)             // 1024
#define NCHUNKS_TOT   (CHUNKS_PER_GT * (G_TOT / GTILE)) // 32768

__device__ __forceinline__ unsigned long long pack2(float lo, float hi) {
    unsigned long long r;
    asm("mov.b64 %0, {%1, %2};" : "=l"(r) : "f"(lo), "f"(hi));
    return r;
}
__device__ __forceinline__ void unpack2(unsigned long long v, float& lo, float& hi) {
    asm("mov.b64 {%0, %1}, %2;" : "=f"(lo), "=f"(hi) : "l"(v));
}
// d = a * b + d  (packed f32x2 — ptxas never auto-emits FFMA2)
__device__ __forceinline__ void ffma2(unsigned long long& d,
                                      unsigned long long a, unsigned long long b) {
    asm("fma.rn.f32x2 %0, %1, %2, %0;" : "+l"(d) : "l"(a), "l"(b));
}
__device__ __forceinline__ uint32_t smem_u32(const void* p) {
    return (uint32_t)__cvta_generic_to_shared(p);
}
__device__ __forceinline__ void cp_async16(uint32_t dst, const void* src) {
    asm volatile("cp.async.cg.shared.global [%0], [%1], 16;" :: "r"(dst), "l"(src));
}

__global__ void __launch_bounds__(BLOCK, 3)
bd_kernel(const float* __restrict__ x, const float* __restrict__ W,
          float* __restrict__ out)
{
    // 3 stages * 8 rows * 32 groups * 16 floats * 4B = 48 KB
    __shared__ float xs[STAGES][CHUNK_ROWS * GTILE * WSZ];

    const int tid = threadIdx.x;
    const int hq  = tid & (HSPLIT - 1);   // h-pair (0..7)
    const int gl  = tid >> 3;             // local group (0..31)

    // ---- flattened persistent split: single wave, balanced to ±1 chunk
    const int nCTA = gridDim.x;
    const int bid  = blockIdx.x;
    const int c0 = (int)((long long)bid       * NCHUNKS_TOT / nCTA);
    const int c1 = (int)((long long)(bid + 1) * NCHUNKS_TOT / nCTA);

    // coalesced chunk loader: 16 KB = 1024 x 16B, 4 cp.async per thread
    auto load_chunk = [&](int c, int slot) {
        const int gt      = c >> 10;                 // c / CHUNKS_PER_GT
        const int rowbase = (c & 1023) * CHUNK_ROWS;
        const float* src0 = x + (size_t)rowbase * ROWSTRIDE + gt * (GTILE * WSZ);
#pragma unroll
        for (int j = 0; j < 4; ++j) {
            int idx = tid + j * BLOCK;               // 0..1023
            int rl  = idx >> 7;                      // row within chunk
            int off = idx & 127;                     // 16B unit in 2KB row slice
            uint32_t dst = smem_u32(&xs[slot][rl * (GTILE * WSZ)]) + off * 16;
            cp_async16(dst, (const void*)(src0 + (size_t)rl * ROWSTRIDE + off * 4));
        }
        asm volatile("cp.async.commit_group;");
    };

    // ---- prologue: fill pipeline (always commit a group to keep counts aligned)
    for (int i = 0; i < STAGES - 1; ++i) {
        if (c0 + i < c1) load_chunk(c0 + i, i);
        else             asm volatile("cp.async.commit_group;");
    }

    unsigned long long w2[WSZ / 2][2];
    int cur_gt = -1;

    for (int c = c0; c < c1; ++c) {
        const int k = c - c0;
        asm volatile("cp.async.wait_group %0;" :: "n"(STAGES - 2));
        __syncthreads();   // chunk c resident; slot (k+2)%3 reads all done (iter c-1)

        // prefetch chunk c+2 into slot (k+2)%3 — issued before compute
        const int cn = c + STAGES - 1;
        if (cn < c1) load_chunk(cn, (cn - c0) % STAGES);
        else         asm volatile("cp.async.commit_group;");

        const int gt = c >> 10;
        if (gt != cur_gt) {   // weight reload: <=1 crossing per CTA, L2-hot
            cur_gt = gt;
            const float* wg = W + (size_t)(gt * GTILE + gl) * (WSZ * HDIM) + hq * 2;
#pragma unroll
            for (int k2 = 0; k2 < WSZ / 2; ++k2) {
                float2 a = *(const float2*)(wg + (2 * k2)     * HDIM);
                float2 b = *(const float2*)(wg + (2 * k2 + 1) * HDIM);
                w2[k2][0] = pack2(a.x, b.x);
                w2[k2][1] = pack2(a.y, b.y);
            }
        }

        const int slot     = k % STAGES;
        const int rowbase  = (c & 1023) * CHUNK_ROWS;
        const float* xrow0 = &xs[slot][gl * WSZ];
        float* optr = out + (size_t)rowbase * (G_TOT * HDIM)
                          + (size_t)(gt * GTILE + gl) * HDIM + hq * 2;

#pragma unroll
        for (int rl = 0; rl < CHUNK_ROWS; ++rl) {
            const ulonglong2* xq =
                (const ulonglong2*)(xrow0 + rl * (GTILE * WSZ));
            ulonglong2 q0 = xq[0], q1 = xq[1], q2 = xq[2], q3 = xq[3];
            unsigned long long xv[8] = {q0.x, q0.y, q1.x, q1.y,
                                        q2.x, q2.y, q3.x, q3.y};
            unsigned long long a0 = 0ull, a1 = 0ull;
#pragma unroll
            for (int k2 = 0; k2 < 8; ++k2) {
                ffma2(a0, xv[k2], w2[k2][0]);
                ffma2(a1, xv[k2], w2[k2][1]);
            }
            float l0, h0, l1, h1;
            unpack2(a0, l0, h0);
            unpack2(a1, l1, h1);
            float2 o;
            o.x = fmaxf(l0 + h0, 0.0f);   // k-pair horizontal reduce + ReLU
            o.y = fmaxf(l1 + h1, 0.0f);
            *(float2*)optr = o;           // warp writes 256B contiguous
            optr += G_TOT * HDIM;
        }
    }
}

extern "C" void kernel_launch(void* const* d_in, const int* in_sizes, int n_in,
                              void* d_out, int out_size) {
    const float* x = (const float*)d_in[0];   // (8192, 16384) f32
    const float* W = (const float*)d_in[1];   // (1024, 16, 16) f32
    float* out = (float*)d_out;               // (8192, 16384) f32

    int sms = 148;
    cudaDeviceGetAttribute(&sms, cudaDevAttrMultiProcessorCount, 0);
    dim3 grid(sms * 3);                        // exactly one wave at occ=3
    bd_kernel<<<grid, BLOCK>>>(x, W, out);
}